// round 1
// baseline (speedup 1.0000x reference)
#include <cuda_runtime.h>
#include <math.h>

// ---------------------------------------------------------------------------
// Problem constants (B=1)
// ---------------------------------------------------------------------------
#define ZD 8
#define HD_ 60
#define WD 120
#define CDIM 192
#define NHEADS 6
#define HEADDIM 32
#define WS0 2
#define WS1 6
#define WS2 12
#define NTOK 57600            // Z*H*W
#define NWIN 400              // nZ*nH*nL = 4*10*10
#define NLOC 144              // WS0*WS1*WS2
#define NZ 4
#define NH 10
#define NL 10

// ---------------------------------------------------------------------------
// Scratch (static device globals — allocation-free)
// ---------------------------------------------------------------------------
__device__ float g_hw[NTOK * CDIM];       // windowed modulated input / ln2 out
__device__ float g_qkv[NTOK * 576];       // qkv per windowed token
__device__ float g_attnout[NTOK * CDIM];  // attention output (window layout)
__device__ float g_y[NTOK * CDIM];        // post-MSA residual stream
__device__ float g_hidden[NTOK * 768];    // MLP hidden

// ---------------------------------------------------------------------------
// Helpers
// ---------------------------------------------------------------------------
__device__ __forceinline__ float warpsum(float v) {
#pragma unroll
    for (int o = 16; o > 0; o >>= 1) v += __shfl_xor_sync(0xffffffffu, v, o);
    return v;
}

// window/local -> rolled grid coords -> original token index
__device__ __forceinline__ int win_to_orig(int w, int n) {
    int il = w % NL, ih = (w / NL) % NH, iz = w / (NL * NH);
    int z = n / (WS1 * WS2), hh = (n / WS2) % WS1, l = n % WS2;
    int gz = iz * WS0 + z, gh = ih * WS1 + hh, gl = il * WS2 + l;
    int oz = (gz + 1) & 7;
    int oh = gh + 3; if (oh >= HD_) oh -= HD_;
    int ol = gl + 6; if (ol >= WD) ol -= WD;
    return (oz * HD_ + oh) * WD + ol;
}

// ---------------------------------------------------------------------------
// K1: LayerNorm1 + adaLN modulate + roll + window partition (gather)
// one warp per windowed token
// ---------------------------------------------------------------------------
__global__ __launch_bounds__(256) void k_ln1(const float* __restrict__ x,
                                             const float* __restrict__ cond,
                                             const float* __restrict__ g,
                                             const float* __restrict__ b) {
    int t = blockIdx.x * 8 + (threadIdx.x >> 5);
    int lane = threadIdx.x & 31;
    int w = t / NLOC, n = t - w * NLOC;
    int src = win_to_orig(w, n);
    const float* xr = x + (size_t)src * CDIM;
    float v[6]; float s = 0.f;
#pragma unroll
    for (int i = 0; i < 6; i++) { v[i] = xr[lane + 32 * i]; s += v[i]; }
    s = warpsum(s);
    float mu = s * (1.f / 192.f);
    float vs = 0.f;
#pragma unroll
    for (int i = 0; i < 6; i++) { float d = v[i] - mu; vs += d * d; }
    vs = warpsum(vs);
    float rstd = rsqrtf(vs * (1.f / 192.f) + 1e-5f);
    float* o = g_hw + (size_t)t * CDIM;
#pragma unroll
    for (int i = 0; i < 6; i++) {
        int c = lane + 32 * i;
        float val = (v[i] - mu) * rstd * g[c] + b[c];
        // sh_msa = cond[0:192), sc_msa = cond[192:384)
        o[c] = val * (1.f + cond[192 + c]) + cond[c];
    }
}

// ---------------------------------------------------------------------------
// K5: LayerNorm2 + adaLN modulate (no gather): y -> g_hw
// ---------------------------------------------------------------------------
__global__ __launch_bounds__(256) void k_ln2(const float* __restrict__ cond,
                                             const float* __restrict__ g,
                                             const float* __restrict__ b) {
    int t = blockIdx.x * 8 + (threadIdx.x >> 5);
    int lane = threadIdx.x & 31;
    const float* xr = g_y + (size_t)t * CDIM;
    float v[6]; float s = 0.f;
#pragma unroll
    for (int i = 0; i < 6; i++) { v[i] = xr[lane + 32 * i]; s += v[i]; }
    s = warpsum(s);
    float mu = s * (1.f / 192.f);
    float vs = 0.f;
#pragma unroll
    for (int i = 0; i < 6; i++) { float d = v[i] - mu; vs += d * d; }
    vs = warpsum(vs);
    float rstd = rsqrtf(vs * (1.f / 192.f) + 1e-5f);
    float* o = g_hw + (size_t)t * CDIM;
#pragma unroll
    for (int i = 0; i < 6; i++) {
        int c = lane + 32 * i;
        float val = (v[i] - mu) * rstd * g[c] + b[c];
        // sh_mlp = cond[576:768), sc_mlp = cond[768:960)
        o[c] = val * (1.f + cond[768 + c]) + cond[576 + c];
    }
}

// ---------------------------------------------------------------------------
// Tiled SGEMM: C[M,N] = A[M,K] @ B[K,N] + bias, with fused epilogues.
// BM=128, BN=64, BK=16, 256 threads, each thread 8x4 outputs.
// MODE 0: plain +bias (QKV)
// MODE 1: proj: scatter to original token order, y = x + gt_msa * val
// MODE 2: fc1: exact GeLU
// MODE 3: fc2: out = y + gt_mlp * val
// ---------------------------------------------------------------------------
template <int MODE>
__global__ __launch_bounds__(256) void k_gemm(const float* __restrict__ A,
                                              const float* __restrict__ B,
                                              const float* __restrict__ bias,
                                              float* __restrict__ Cout,
                                              int K, int Ncols,
                                              const float* __restrict__ res,
                                              const float* __restrict__ cond) {
    __shared__ float As[16][128];
    __shared__ float Bs[16][64];
    int tid = threadIdx.x;
    int tx = tid & 15;   // col group
    int ty = tid >> 4;   // row group
    const float* Ab = A + (size_t)blockIdx.y * 128 * K;
    const float* Bb = B + blockIdx.x * 64;

    float acc[8][4];
#pragma unroll
    for (int i = 0; i < 8; i++)
#pragma unroll
        for (int j = 0; j < 4; j++) acc[i][j] = 0.f;

    for (int k0 = 0; k0 < K; k0 += 16) {
#pragma unroll
        for (int i = 0; i < 2; i++) {
            int idx = tid + i * 256;
            int row = idx >> 2, qd = idx & 3;
            float4 a = *(const float4*)(Ab + (size_t)row * K + k0 + qd * 4);
            As[qd * 4 + 0][row] = a.x;
            As[qd * 4 + 1][row] = a.y;
            As[qd * 4 + 2][row] = a.z;
            As[qd * 4 + 3][row] = a.w;
        }
        {
            int row = tid >> 4, qd = tid & 15;
            *(float4*)&Bs[row][qd * 4] =
                *(const float4*)(Bb + (size_t)(k0 + row) * Ncols + qd * 4);
        }
        __syncthreads();
#pragma unroll
        for (int k = 0; k < 16; k++) {
            float af[8], bf[4];
#pragma unroll
            for (int i = 0; i < 8; i++) af[i] = As[k][ty * 8 + i];
#pragma unroll
            for (int j = 0; j < 4; j++) bf[j] = Bs[k][tx * 4 + j];
#pragma unroll
            for (int i = 0; i < 8; i++)
#pragma unroll
                for (int j = 0; j < 4; j++) acc[i][j] = fmaf(af[i], bf[j], acc[i][j]);
        }
        __syncthreads();
    }

    int col0 = blockIdx.x * 64 + tx * 4;
#pragma unroll
    for (int i = 0; i < 8; i++) {
        int row = blockIdx.y * 128 + ty * 8 + i;
        if (MODE == 0) {
            float* dst = Cout + (size_t)row * Ncols + col0;
#pragma unroll
            for (int j = 0; j < 4; j++) dst[j] = acc[i][j] + bias[col0 + j];
        } else if (MODE == 1) {
            int w = row / NLOC, n = row - w * NLOC;
            int o = win_to_orig(w, n);
#pragma unroll
            for (int j = 0; j < 4; j++) {
                int c = col0 + j;
                float val = acc[i][j] + bias[c];
                Cout[(size_t)o * CDIM + c] =
                    res[(size_t)o * CDIM + c] + cond[384 + c] * val;
            }
        } else if (MODE == 2) {
            float* dst = Cout + (size_t)row * Ncols + col0;
#pragma unroll
            for (int j = 0; j < 4; j++) {
                float xg = acc[i][j] + bias[col0 + j];
                dst[j] = 0.5f * xg * (1.f + erff(xg * 0.70710678118654752f));
            }
        } else {  // MODE 3
#pragma unroll
            for (int j = 0; j < 4; j++) {
                int c = col0 + j;
                float val = acc[i][j] + bias[c];
                Cout[(size_t)row * CDIM + c] =
                    res[(size_t)row * CDIM + c] + cond[960 + c] * val;
            }
        }
    }
}

// ---------------------------------------------------------------------------
// K3: fused window attention. One block per (window, head). 160 threads.
// threads 0..143 each own one query row; flash-style online softmax.
// Relative-position bias gathered from bias_table, mask computed in closed form.
// ---------------------------------------------------------------------------
__global__ __launch_bounds__(160) void k_attn(const float* __restrict__ qkv,
                                              const float* __restrict__ bias_table,
                                              float* __restrict__ outp) {
    int w = blockIdx.x / NHEADS;
    int head = blockIdx.x - w * NHEADS;
    __shared__ float ks[NLOC][32];
    __shared__ float vs[NLOC][32];
    __shared__ float qs[NLOC][33];
    __shared__ int cmi[NLOC];
    __shared__ int lblm[NLOC];

    int tid = threadIdx.x;
    const float* base = qkv + (size_t)w * NLOC * 576;

    for (int idx = tid; idx < NLOC * 8; idx += 160) {
        int row = idx >> 3, f = idx & 7;
        const float* rb = base + (size_t)row * 576 + head * 32 + f * 4;
        float4 qv = *(const float4*)(rb);
        float4 kv = *(const float4*)(rb + 192);
        float4 vv = *(const float4*)(rb + 384);
        qs[row][f * 4 + 0] = qv.x; qs[row][f * 4 + 1] = qv.y;
        qs[row][f * 4 + 2] = qv.z; qs[row][f * 4 + 3] = qv.w;
        *(float4*)&ks[row][f * 4] = kv;
        *(float4*)&vs[row][f * 4] = vv;
    }
    int il = w % NL, ih = (w / NL) % NH, iz = w / (NL * NH);
    (void)il;
    if (tid < NLOC) {
        int z = tid / 72, hh = (tid / 12) % 6, l = tid % 12;
        cmi[tid] = 1656 * z + 138 * hh - l;  // 828*2z + 23*6h - l
        int gz = iz * WS0 + z, gh = ih * WS1 + hh;
        int zseg = gz < 6 ? 0 : (gz < 7 ? 1 : 2);
        int hseg = gh < 54 ? 0 : (gh < 57 ? 1 : 2);
        lblm[tid] = zseg * 3 + hseg;
    }
    __syncthreads();

    if (tid < NLOC) {
        float q[32];
#pragma unroll
        for (int d = 0; d < 32; d++) q[d] = qs[tid][d] * 0.17677669529663687f;
        int z1 = tid / 72, h1 = (tid / 12) % 6, l1 = tid % 12;
        int cn = 828 * z1 + 23 * h1 + l1 + 11;
        int mylbl = lblm[tid];
        int typ = iz * NH + ih;
        const float* bt = bias_table + typ * NHEADS + head;

        float acc[32];
#pragma unroll
        for (int d = 0; d < 32; d++) acc[d] = 0.f;
        float mrun = -1e30f, lrun = 0.f;

        for (int m = 0; m < NLOC; m++) {
            float s = 0.f;
#pragma unroll
            for (int f = 0; f < 8; f++) {
                float4 kk = *(const float4*)&ks[m][f * 4];
                s = fmaf(q[f * 4 + 0], kk.x, s);
                s = fmaf(q[f * 4 + 1], kk.y, s);
                s = fmaf(q[f * 4 + 2], kk.z, s);
                s = fmaf(q[f * 4 + 3], kk.w, s);
            }
            int pidx = cn + cmi[m];
            s += __ldg(bt + (size_t)pidx * 240);
            if (lblm[m] != mylbl) s -= 100.f;

            if (s > mrun) {
                float corr = __expf(mrun - s);
                lrun = lrun * corr + 1.f;
#pragma unroll
                for (int d = 0; d < 32; d++)
                    acc[d] = fmaf(acc[d], corr, vs[m][d]);
                mrun = s;
            } else {
                float p = __expf(s - mrun);
                lrun += p;
#pragma unroll
                for (int d = 0; d < 32; d++)
                    acc[d] = fmaf(p, vs[m][d], acc[d]);
            }
        }
        float inv = 1.f / lrun;
        float* orow = outp + ((size_t)(w * NLOC + tid)) * CDIM + head * 32;
#pragma unroll
        for (int d = 0; d < 32; d++) orow[d] = acc[d] * inv;
    }
}

// ---------------------------------------------------------------------------
// Launch
// ---------------------------------------------------------------------------
extern "C" void kernel_launch(void* const* d_in, const int* in_sizes, int n_in,
                              void* d_out, int out_size) {
    const float* x          = (const float*)d_in[0];
    const float* cond       = (const float*)d_in[1];
    const float* g1         = (const float*)d_in[2];
    const float* bt1        = (const float*)d_in[3];
    const float* w_qkv      = (const float*)d_in[4];
    const float* b_qkv      = (const float*)d_in[5];
    const float* bias_table = (const float*)d_in[6];
    const float* w_proj     = (const float*)d_in[7];
    const float* b_proj     = (const float*)d_in[8];
    const float* g2         = (const float*)d_in[9];
    const float* bt2        = (const float*)d_in[10];
    const float* w_fc1      = (const float*)d_in[11];
    const float* b_fc1      = (const float*)d_in[12];
    const float* w_fc2      = (const float*)d_in[13];
    const float* b_fc2      = (const float*)d_in[14];
    float* out = (float*)d_out;

    float *hw, *qkvb, *ao, *yb, *hid;
    cudaGetSymbolAddress((void**)&hw, g_hw);
    cudaGetSymbolAddress((void**)&qkvb, g_qkv);
    cudaGetSymbolAddress((void**)&ao, g_attnout);
    cudaGetSymbolAddress((void**)&yb, g_y);
    cudaGetSymbolAddress((void**)&hid, g_hidden);

    // 1. LN1 + modulate + roll + window partition
    k_ln1<<<NTOK / 8, 256>>>(x, cond, g1, bt1);

    // 2. QKV GEMM: (57600,192) @ (192,576)
    k_gemm<0><<<dim3(576 / 64, NTOK / 128), 256>>>(hw, w_qkv, b_qkv, qkvb,
                                                   192, 576, nullptr, nullptr);

    // 3. Window attention
    k_attn<<<NWIN * NHEADS, 160>>>(qkvb, bias_table, ao);

    // 4. Proj GEMM + un-window/unroll scatter + gated residual -> y
    k_gemm<1><<<dim3(192 / 64, NTOK / 128), 256>>>(ao, w_proj, b_proj, yb,
                                                   192, 192, x, cond);

    // 5. LN2 + modulate
    k_ln2<<<NTOK / 8, 256>>>(cond, g2, bt2);

    // 6. FC1 GEMM + exact GeLU
    k_gemm<2><<<dim3(768 / 64, NTOK / 128), 256>>>(hw, w_fc1, b_fc1, hid,
                                                   192, 768, nullptr, nullptr);

    // 7. FC2 GEMM + gated residual -> output
    k_gemm<3><<<dim3(192 / 64, NTOK / 128), 256>>>(hid, w_fc2, b_fc2, out,
                                                   768, 192, yb, cond);
}

// round 3
// speedup vs baseline: 1.0842x; 1.0842x over previous
#include <cuda_runtime.h>
#include <cuda_bf16.h>
#include <math.h>
#include <stdint.h>

// ---------------------------------------------------------------------------
// Problem constants (B=1)
// ---------------------------------------------------------------------------
#define ZD 8
#define HD_ 60
#define WD 120
#define CDIM 192
#define NHEADS 6
#define WS0 2
#define WS1 6
#define WS2 12
#define NTOK 57600
#define NWIN 400
#define NLOC 144
#define NZ 4
#define NH 10
#define NL 10

// ---------------------------------------------------------------------------
// Scratch (static device globals — allocation-free)
// A' split-K layout: cols [0,K)=hi, [K,2K)=lo, [2K,3K)=hi
// B' split-K layout: cols [0,K)=hi, [K,2K)=hi, [2K,3K)=lo   (rows=N, K-major)
// ---------------------------------------------------------------------------
__device__ __nv_bfloat16 g_A1[NTOK * 576];      // ln1/ln2 out, split (K=192)
__device__ float         g_qkv[NTOK * 576];     // qkv fp32
__device__ __nv_bfloat16 g_Aattn[NTOK * 576];   // attn out, split (K=192)
__device__ float         g_y[NTOK * 192];       // post-MSA residual
__device__ __nv_bfloat16 g_A2[NTOK * 2304];     // fc1 out, split (K=768)
__device__ __nv_bfloat16 g_Bqkv[576 * 576];
__device__ __nv_bfloat16 g_Bproj[192 * 576];
__device__ __nv_bfloat16 g_Bfc1[768 * 576];
__device__ __nv_bfloat16 g_Bfc2[192 * 2304];

// ---------------------------------------------------------------------------
// Helpers
// ---------------------------------------------------------------------------
__device__ __forceinline__ float warpsum(float v) {
#pragma unroll
    for (int o = 16; o > 0; o >>= 1) v += __shfl_xor_sync(0xffffffffu, v, o);
    return v;
}

__device__ __forceinline__ int win_to_orig(int w, int n) {
    int ih = (w / NL) % NH, iz = w / (NL * NH);
    int il = w % NL;
    int z = n / (WS1 * WS2), hh = (n / WS2) % WS1, l = n % WS2;
    int gz = iz * WS0 + z, gh = ih * WS1 + hh, gl = il * WS2 + l;
    int oz = (gz + 1) & 7;
    int oh = gh + 3; if (oh >= HD_) oh -= HD_;
    int ol = gl + 6; if (ol >= WD) ol -= WD;
    return (oz * HD_ + oh) * WD + ol;
}

__device__ __forceinline__ uint32_t cvta_smem(const void* p) {
    return (uint32_t)__cvta_generic_to_shared(p);
}

__device__ __forceinline__ void split_store(__nv_bfloat16* base, size_t stride3,
                                            size_t row, int K, int c, float v) {
    __nv_bfloat16 hi = __float2bfloat16(v);
    __nv_bfloat16 lo = __float2bfloat16(v - __bfloat162float(hi));
    size_t rb = row * stride3;
    base[rb + c] = hi;
    base[rb + K + c] = lo;
    base[rb + 2 * K + c] = hi;
}

// ---------------------------------------------------------------------------
// Weight prep: W[K,N] fp32 -> B'[N, 3K] bf16 (hi, hi, lo)
// ---------------------------------------------------------------------------
__global__ void k_wprep(const float* __restrict__ W, __nv_bfloat16* __restrict__ Bp,
                        int K, int N) {
    int i = blockIdx.x * 256 + threadIdx.x;
    if (i >= K * N) return;
    int k = i / N, n = i - k * N;
    float w = W[i];
    __nv_bfloat16 hi = __float2bfloat16(w);
    __nv_bfloat16 lo = __float2bfloat16(w - __bfloat162float(hi));
    size_t base = (size_t)n * 3 * K;
    Bp[base + k] = hi;
    Bp[base + K + k] = hi;
    Bp[base + 2 * K + k] = lo;
}

// ---------------------------------------------------------------------------
// K1: LN1 + modulate + roll + window gather -> split A'
// ---------------------------------------------------------------------------
__global__ __launch_bounds__(256) void k_ln1(const float* __restrict__ x,
                                             const float* __restrict__ cond,
                                             const float* __restrict__ g,
                                             const float* __restrict__ b) {
    int t = blockIdx.x * 8 + (threadIdx.x >> 5);
    int lane = threadIdx.x & 31;
    int w = t / NLOC, n = t - w * NLOC;
    int src = win_to_orig(w, n);
    const float* xr = x + (size_t)src * CDIM;
    float v[6]; float s = 0.f;
#pragma unroll
    for (int i = 0; i < 6; i++) { v[i] = xr[lane + 32 * i]; s += v[i]; }
    s = warpsum(s);
    float mu = s * (1.f / 192.f);
    float vs = 0.f;
#pragma unroll
    for (int i = 0; i < 6; i++) { float d = v[i] - mu; vs += d * d; }
    vs = warpsum(vs);
    float rstd = rsqrtf(vs * (1.f / 192.f) + 1e-5f);
#pragma unroll
    for (int i = 0; i < 6; i++) {
        int c = lane + 32 * i;
        float val = (v[i] - mu) * rstd * g[c] + b[c];
        val = val * (1.f + cond[192 + c]) + cond[c];
        split_store(g_A1, 576, (size_t)t, 192, c, val);
    }
}

// ---------------------------------------------------------------------------
// K5: LN2 + modulate -> split A'
// ---------------------------------------------------------------------------
__global__ __launch_bounds__(256) void k_ln2(const float* __restrict__ cond,
                                             const float* __restrict__ g,
                                             const float* __restrict__ b) {
    int t = blockIdx.x * 8 + (threadIdx.x >> 5);
    int lane = threadIdx.x & 31;
    const float* xr = g_y + (size_t)t * CDIM;
    float v[6]; float s = 0.f;
#pragma unroll
    for (int i = 0; i < 6; i++) { v[i] = xr[lane + 32 * i]; s += v[i]; }
    s = warpsum(s);
    float mu = s * (1.f / 192.f);
    float vs = 0.f;
#pragma unroll
    for (int i = 0; i < 6; i++) { float d = v[i] - mu; vs += d * d; }
    vs = warpsum(vs);
    float rstd = rsqrtf(vs * (1.f / 192.f) + 1e-5f);
#pragma unroll
    for (int i = 0; i < 6; i++) {
        int c = lane + 32 * i;
        float val = (v[i] - mu) * rstd * g[c] + b[c];
        val = val * (1.f + cond[768 + c]) + cond[576 + c];
        split_store(g_A1, 576, (size_t)t, 192, c, val);
    }
}

// ---------------------------------------------------------------------------
// Tensor-core GEMM via mma.sync m16n8k16 bf16.
// Block tile 128x192, 8 warps (2x4), warp tile 64x48.
// K looped in 64-bf16 chunks; SW128-swizzled single smem buffer with
// register-staged prefetch of the next chunk.
// MODE 0: qkv +bias -> fp32
// MODE 1: proj: scatter + gated residual -> g_y
// MODE 2: fc1: GeLU -> split bf16 (K=768 layout)
// MODE 3: fc2: gated residual -> out
// ---------------------------------------------------------------------------
template <int MODE>
__global__ __launch_bounds__(256, 1) void k_tc_gemm(
    const __nv_bfloat16* __restrict__ A, const __nv_bfloat16* __restrict__ Bw,
    const float* __restrict__ bias, int Keff,
    float* __restrict__ fout, __nv_bfloat16* __restrict__ sout,
    const float* __restrict__ res, const float* __restrict__ cond) {
    __shared__ __align__(1024) unsigned char smA[16384];   // 128 rows x 128B
    __shared__ __align__(1024) unsigned char smB[24576];   // 192 rows x 128B

    const int tid = threadIdx.x;
    const int lane = tid & 31;
    const int wid = tid >> 5;
    const int warp_m = (wid & 1) * 64;
    const int warp_n = (wid >> 1) * 48;

    const int rowbase = blockIdx.y * 128;
    const int colbase = blockIdx.x * 192;
    const int nchunks = Keff >> 6;

    const __nv_bfloat16* Arow = A + (size_t)rowbase * Keff;
    const __nv_bfloat16* Brow = Bw + (size_t)colbase * Keff;

    float acc[4][6][4];
#pragma unroll
    for (int mt = 0; mt < 4; mt++)
#pragma unroll
        for (int nt = 0; nt < 6; nt++)
#pragma unroll
            for (int i = 0; i < 4; i++) acc[mt][nt][i] = 0.f;

    // staging registers
    uint4 stA[4], stB[6];
    // per-thread staging coords
    int ar[4], as_[4], br[6], bs_[6];
#pragma unroll
    for (int i = 0; i < 4; i++) {
        int idx = tid + i * 256;
        ar[i] = idx >> 3; as_[i] = idx & 7;
    }
#pragma unroll
    for (int i = 0; i < 6; i++) {
        int idx = tid + i * 256;
        br[i] = idx >> 3; bs_[i] = idx & 7;
    }

    auto gload = [&](int ch) {
        const __nv_bfloat16* Ach = Arow + ch * 64;
        const __nv_bfloat16* Bch = Brow + ch * 64;
#pragma unroll
        for (int i = 0; i < 4; i++)
            stA[i] = *(const uint4*)(Ach + (size_t)ar[i] * Keff + as_[i] * 8);
#pragma unroll
        for (int i = 0; i < 6; i++)
            stB[i] = *(const uint4*)(Bch + (size_t)br[i] * Keff + bs_[i] * 8);
    };
    auto sstore = [&]() {
#pragma unroll
        for (int i = 0; i < 4; i++) {
            uint32_t off = (uint32_t)(ar[i] * 128 + ((as_[i] ^ (ar[i] & 7)) << 4));
            *(uint4*)(smA + off) = stA[i];
        }
#pragma unroll
        for (int i = 0; i < 6; i++) {
            uint32_t off = (uint32_t)(br[i] * 128 + ((bs_[i] ^ (br[i] & 7)) << 4));
            *(uint4*)(smB + off) = stB[i];
        }
    };

    // ldmatrix base addresses (per-lane, fixed rows; k-seg varies)
    const uint32_t smA_u = cvta_smem(smA);
    const uint32_t smB_u = cvta_smem(smB);

    gload(0);
    sstore();
    __syncthreads();

    for (int ch = 0; ch < nchunks; ch++) {
        if (ch + 1 < nchunks) gload(ch + 1);

#pragma unroll
        for (int kk = 0; kk < 4; kk++) {
            uint32_t af[4][4];
#pragma unroll
            for (int mt = 0; mt < 4; mt++) {
                int r = warp_m + mt * 16 + (lane & 15);
                int seg = kk * 2 + (lane >> 4);
                uint32_t addr = smA_u + r * 128 + (((seg ^ (r & 7)) & 7) << 4);
                asm volatile(
                    "ldmatrix.sync.aligned.m8n8.x4.shared.b16 {%0,%1,%2,%3}, [%4];"
                    : "=r"(af[mt][0]), "=r"(af[mt][1]), "=r"(af[mt][2]), "=r"(af[mt][3])
                    : "r"(addr));
            }
            uint32_t bf[6][2];
#pragma unroll
            for (int nt = 0; nt < 6; nt++) {
                int r = warp_n + nt * 8 + (lane & 7);
                int seg = kk * 2 + ((lane >> 3) & 1);
                uint32_t addr = smB_u + r * 128 + (((seg ^ (r & 7)) & 7) << 4);
                asm volatile(
                    "ldmatrix.sync.aligned.m8n8.x2.shared.b16 {%0,%1}, [%2];"
                    : "=r"(bf[nt][0]), "=r"(bf[nt][1])
                    : "r"(addr));
            }
#pragma unroll
            for (int mt = 0; mt < 4; mt++)
#pragma unroll
                for (int nt = 0; nt < 6; nt++) {
                    asm volatile(
                        "mma.sync.aligned.m16n8k16.row.col.f32.bf16.bf16.f32 "
                        "{%0,%1,%2,%3}, {%4,%5,%6,%7}, {%8,%9}, {%0,%1,%2,%3};"
                        : "+f"(acc[mt][nt][0]), "+f"(acc[mt][nt][1]),
                          "+f"(acc[mt][nt][2]), "+f"(acc[mt][nt][3])
                        : "r"(af[mt][0]), "r"(af[mt][1]), "r"(af[mt][2]), "r"(af[mt][3]),
                          "r"(bf[nt][0]), "r"(bf[nt][1]));
                }
        }
        __syncthreads();
        if (ch + 1 < nchunks) {
            sstore();
            __syncthreads();
        }
    }

    // -------------------- epilogue --------------------
#pragma unroll
    for (int mt = 0; mt < 4; mt++) {
#pragma unroll
        for (int half = 0; half < 2; half++) {
            int row = rowbase + warp_m + mt * 16 + (lane >> 2) + half * 8;
            int orow = 0;
            if (MODE == 1) orow = win_to_orig(row / NLOC, row % NLOC);
#pragma unroll
            for (int nt = 0; nt < 6; nt++) {
#pragma unroll
                for (int e = 0; e < 2; e++) {
                    float v = acc[mt][nt][half * 2 + e];
                    int c = colbase + warp_n + nt * 8 + (lane & 3) * 2 + e;
                    if (MODE == 0) {
                        fout[(size_t)row * 576 + c] = v + bias[c];
                    } else if (MODE == 1) {
                        float val = v + bias[c];
                        fout[(size_t)orow * 192 + c] =
                            res[(size_t)orow * 192 + c] + cond[384 + c] * val;
                    } else if (MODE == 2) {
                        float xg = v + bias[c];
                        float gl = 0.5f * xg * (1.f + erff(xg * 0.70710678118654752f));
                        split_store(sout, 2304, (size_t)row, 768, c, gl);
                    } else {
                        float val = v + bias[c];
                        fout[(size_t)row * 192 + c] =
                            res[(size_t)row * 192 + c] + cond[960 + c] * val;
                    }
                }
            }
        }
    }
}

// ---------------------------------------------------------------------------
// K3: fused window attention (fp32; writes split bf16 for proj GEMM)
// ---------------------------------------------------------------------------
__global__ __launch_bounds__(160) void k_attn(const float* __restrict__ qkv,
                                              const float* __restrict__ bias_table) {
    int w = blockIdx.x / NHEADS;
    int head = blockIdx.x - w * NHEADS;
    __shared__ float ks[NLOC][32];
    __shared__ float vs[NLOC][32];
    __shared__ float qs[NLOC][33];
    __shared__ int cmi[NLOC];
    __shared__ int lblm[NLOC];

    int tid = threadIdx.x;
    const float* base = qkv + (size_t)w * NLOC * 576;

    for (int idx = tid; idx < NLOC * 8; idx += 160) {
        int row = idx >> 3, f = idx & 7;
        const float* rb = base + (size_t)row * 576 + head * 32 + f * 4;
        float4 qv = *(const float4*)(rb);
        float4 kv = *(const float4*)(rb + 192);
        float4 vv = *(const float4*)(rb + 384);
        qs[row][f * 4 + 0] = qv.x; qs[row][f * 4 + 1] = qv.y;
        qs[row][f * 4 + 2] = qv.z; qs[row][f * 4 + 3] = qv.w;
        *(float4*)&ks[row][f * 4] = kv;
        *(float4*)&vs[row][f * 4] = vv;
    }
    int ih = (w / NL) % NH, iz = w / (NL * NH);
    if (tid < NLOC) {
        int z = tid / 72, hh = (tid / 12) % 6, l = tid % 12;
        cmi[tid] = 1656 * z + 138 * hh - l;
        int gz = iz * WS0 + z, gh = ih * WS1 + hh;
        int zseg = gz < 6 ? 0 : (gz < 7 ? 1 : 2);
        int hseg = gh < 54 ? 0 : (gh < 57 ? 1 : 2);
        lblm[tid] = zseg * 3 + hseg;
    }
    __syncthreads();

    if (tid < NLOC) {
        float q[32];
#pragma unroll
        for (int d = 0; d < 32; d++) q[d] = qs[tid][d] * 0.17677669529663687f;
        int z1 = tid / 72, h1 = (tid / 12) % 6, l1 = tid % 12;
        int cn = 828 * z1 + 23 * h1 + l1 + 11;
        int mylbl = lblm[tid];
        int typ = iz * NH + ih;
        const float* bt = bias_table + typ * NHEADS + head;

        float acc[32];
#pragma unroll
        for (int d = 0; d < 32; d++) acc[d] = 0.f;
        float mrun = -1e30f, lrun = 0.f;

        for (int m = 0; m < NLOC; m++) {
            float s = 0.f;
#pragma unroll
            for (int f = 0; f < 8; f++) {
                float4 kk = *(const float4*)&ks[m][f * 4];
                s = fmaf(q[f * 4 + 0], kk.x, s);
                s = fmaf(q[f * 4 + 1], kk.y, s);
                s = fmaf(q[f * 4 + 2], kk.z, s);
                s = fmaf(q[f * 4 + 3], kk.w, s);
            }
            int pidx = cn + cmi[m];
            s += __ldg(bt + (size_t)pidx * 240);
            if (lblm[m] != mylbl) s -= 100.f;

            if (s > mrun) {
                float corr = __expf(mrun - s);
                lrun = lrun * corr + 1.f;
#pragma unroll
                for (int d = 0; d < 32; d++)
                    acc[d] = fmaf(acc[d], corr, vs[m][d]);
                mrun = s;
            } else {
                float p = __expf(s - mrun);
                lrun += p;
#pragma unroll
                for (int d = 0; d < 32; d++)
                    acc[d] = fmaf(p, vs[m][d], acc[d]);
            }
        }
        float inv = 1.f / lrun;
        size_t row = (size_t)(w * NLOC + tid);
        int c0 = head * 32;
#pragma unroll
        for (int d = 0; d < 32; d++) {
            float o = acc[d] * inv;
            split_store(g_Aattn, 576, row, 192, c0 + d, o);
        }
    }
}

// ---------------------------------------------------------------------------
// Launch
// ---------------------------------------------------------------------------
extern "C" void kernel_launch(void* const* d_in, const int* in_sizes, int n_in,
                              void* d_out, int out_size) {
    const float* x          = (const float*)d_in[0];
    const float* cond       = (const float*)d_in[1];
    const float* g1         = (const float*)d_in[2];
    const float* bt1        = (const float*)d_in[3];
    const float* w_qkv      = (const float*)d_in[4];
    const float* b_qkv      = (const float*)d_in[5];
    const float* bias_table = (const float*)d_in[6];
    const float* w_proj     = (const float*)d_in[7];
    const float* b_proj     = (const float*)d_in[8];
    const float* g2         = (const float*)d_in[9];
    const float* bt2        = (const float*)d_in[10];
    const float* w_fc1      = (const float*)d_in[11];
    const float* b_fc1      = (const float*)d_in[12];
    const float* w_fc2      = (const float*)d_in[13];
    const float* b_fc2      = (const float*)d_in[14];
    float* out = (float*)d_out;

    __nv_bfloat16 *a1, *aat, *a2, *bq, *bp, *bf1, *bf2;
    float *qkvb, *yb;
    cudaGetSymbolAddress((void**)&a1, g_A1);
    cudaGetSymbolAddress((void**)&qkvb, g_qkv);
    cudaGetSymbolAddress((void**)&aat, g_Aattn);
    cudaGetSymbolAddress((void**)&yb, g_y);
    cudaGetSymbolAddress((void**)&a2, g_A2);
    cudaGetSymbolAddress((void**)&bq, g_Bqkv);
    cudaGetSymbolAddress((void**)&bp, g_Bproj);
    cudaGetSymbolAddress((void**)&bf1, g_Bfc1);
    cudaGetSymbolAddress((void**)&bf2, g_Bfc2);

    // Weight split/transpose
    k_wprep<<<(192 * 576 + 255) / 256, 256>>>(w_qkv, bq, 192, 576);
    k_wprep<<<(192 * 192 + 255) / 256, 256>>>(w_proj, bp, 192, 192);
    k_wprep<<<(192 * 768 + 255) / 256, 256>>>(w_fc1, bf1, 192, 768);
    k_wprep<<<(768 * 192 + 255) / 256, 256>>>(w_fc2, bf2, 768, 192);

    // 1. LN1 + modulate + window gather -> split A'
    k_ln1<<<NTOK / 8, 256>>>(x, cond, g1, bt1);

    // 2. QKV GEMM: (57600,192) @ (192,576)
    k_tc_gemm<0><<<dim3(3, NTOK / 128), 256>>>(a1, bq, b_qkv, 576,
                                               qkvb, nullptr, nullptr, nullptr);

    // 3. Window attention -> split A'
    k_attn<<<NWIN * NHEADS, 160>>>(qkvb, bias_table);

    // 4. Proj GEMM + scatter + gated residual -> y
    k_tc_gemm<1><<<dim3(1, NTOK / 128), 256>>>(aat, bp, b_proj, 576,
                                               yb, nullptr, x, cond);

    // 5. LN2 + modulate -> split A'
    k_ln2<<<NTOK / 8, 256>>>(cond, g2, bt2);

    // 6. FC1 GEMM + GeLU -> split A2'
    k_tc_gemm<2><<<dim3(4, NTOK / 128), 256>>>(a1, bf1, b_fc1, 576,
                                               nullptr, a2, nullptr, nullptr);

    // 7. FC2 GEMM + gated residual -> out
    k_tc_gemm<3><<<dim3(1, NTOK / 128), 256>>>(a2, bf2, b_fc2, 2304,
                                               out, nullptr, yb, cond);
}

// round 4
// speedup vs baseline: 1.3894x; 1.2815x over previous
#include <cuda_runtime.h>
#include <cuda_bf16.h>
#include <math.h>
#include <stdint.h>

// ---------------------------------------------------------------------------
// Problem constants (B=1)
// ---------------------------------------------------------------------------
#define ZD 8
#define HD_ 60
#define WD 120
#define CDIM 192
#define NHEADS 6
#define WS0 2
#define WS1 6
#define WS2 12
#define NTOK 57600
#define NWIN 400
#define NLOC 144
#define NZ 4
#define NH 10
#define NL 10

// ---------------------------------------------------------------------------
// Scratch. 2-term split-K: A' = [hi | lo], B' = [hi | hi]  (rows=N, K-major)
// => GEMM computes sum_k a_k * hi(b_k): only weight-side bf16 rounding error.
// ---------------------------------------------------------------------------
__device__ __nv_bfloat16 g_A1[NTOK * 384];      // ln1/ln2 out, split (K=192)
__device__ float         g_qkv[NTOK * 576];     // qkv fp32
__device__ __nv_bfloat16 g_Aattn[NTOK * 384];   // attn out, split (K=192)
__device__ float         g_y[NTOK * 192];       // post-MSA residual
__device__ __nv_bfloat16 g_A2[NTOK * 1536];     // fc1 out, split (K=768)
__device__ __nv_bfloat16 g_Bqkv[576 * 384];
__device__ __nv_bfloat16 g_Bproj[192 * 384];
__device__ __nv_bfloat16 g_Bfc1[768 * 384];
__device__ __nv_bfloat16 g_Bfc2[192 * 1536];

// ---------------------------------------------------------------------------
// Helpers
// ---------------------------------------------------------------------------
__device__ __forceinline__ float warpsum(float v) {
#pragma unroll
    for (int o = 16; o > 0; o >>= 1) v += __shfl_xor_sync(0xffffffffu, v, o);
    return v;
}

__device__ __forceinline__ int win_to_orig(int w, int n) {
    int ih = (w / NL) % NH, iz = w / (NL * NH);
    int il = w % NL;
    int z = n / (WS1 * WS2), hh = (n / WS2) % WS1, l = n % WS2;
    int gz = iz * WS0 + z, gh = ih * WS1 + hh, gl = il * WS2 + l;
    int oz = (gz + 1) & 7;
    int oh = gh + 3; if (oh >= HD_) oh -= HD_;
    int ol = gl + 6; if (ol >= WD) ol -= WD;
    return (oz * HD_ + oh) * WD + ol;
}

__device__ __forceinline__ uint32_t cvta_smem(const void* p) {
    return (uint32_t)__cvta_generic_to_shared(p);
}

// A-side split store: hi at [c], lo at [K+c]
__device__ __forceinline__ void split_store(__nv_bfloat16* base, size_t stride2,
                                            size_t row, int K, int c, float v) {
    __nv_bfloat16 hi = __float2bfloat16(v);
    __nv_bfloat16 lo = __float2bfloat16(v - __bfloat162float(hi));
    size_t rb = row * stride2;
    base[rb + c] = hi;
    base[rb + K + c] = lo;
}

__device__ __forceinline__ void cp16(uint32_t saddr, const void* g) {
    asm volatile("cp.async.cg.shared.global [%0], [%1], 16;"
                 :: "r"(saddr), "l"(g));
}

// ---------------------------------------------------------------------------
// Weight prep: W[K,N] fp32 -> B'[N, 2K] bf16 (hi, hi)
// ---------------------------------------------------------------------------
__global__ void k_wprep(const float* __restrict__ W, __nv_bfloat16* __restrict__ Bp,
                        int K, int N) {
    int i = blockIdx.x * 256 + threadIdx.x;
    if (i >= K * N) return;
    int k = i / N, n = i - k * N;
    __nv_bfloat16 hi = __float2bfloat16(W[i]);
    size_t base = (size_t)n * 2 * K;
    Bp[base + k] = hi;
    Bp[base + K + k] = hi;
}

// ---------------------------------------------------------------------------
// K1: LN1 + modulate + roll + window gather -> split A'
// ---------------------------------------------------------------------------
__global__ __launch_bounds__(256) void k_ln1(const float* __restrict__ x,
                                             const float* __restrict__ cond,
                                             const float* __restrict__ g,
                                             const float* __restrict__ b) {
    int t = blockIdx.x * 8 + (threadIdx.x >> 5);
    int lane = threadIdx.x & 31;
    int w = t / NLOC, n = t - w * NLOC;
    int src = win_to_orig(w, n);
    const float* xr = x + (size_t)src * CDIM;
    float v[6]; float s = 0.f;
#pragma unroll
    for (int i = 0; i < 6; i++) { v[i] = xr[lane + 32 * i]; s += v[i]; }
    s = warpsum(s);
    float mu = s * (1.f / 192.f);
    float vs = 0.f;
#pragma unroll
    for (int i = 0; i < 6; i++) { float d = v[i] - mu; vs += d * d; }
    vs = warpsum(vs);
    float rstd = rsqrtf(vs * (1.f / 192.f) + 1e-5f);
#pragma unroll
    for (int i = 0; i < 6; i++) {
        int c = lane + 32 * i;
        float val = (v[i] - mu) * rstd * g[c] + b[c];
        val = val * (1.f + cond[192 + c]) + cond[c];
        split_store(g_A1, 384, (size_t)t, 192, c, val);
    }
}

// ---------------------------------------------------------------------------
// K5: LN2 + modulate -> split A'
// ---------------------------------------------------------------------------
__global__ __launch_bounds__(256) void k_ln2(const float* __restrict__ cond,
                                             const float* __restrict__ g,
                                             const float* __restrict__ b) {
    int t = blockIdx.x * 8 + (threadIdx.x >> 5);
    int lane = threadIdx.x & 31;
    const float* xr = g_y + (size_t)t * CDIM;
    float v[6]; float s = 0.f;
#pragma unroll
    for (int i = 0; i < 6; i++) { v[i] = xr[lane + 32 * i]; s += v[i]; }
    s = warpsum(s);
    float mu = s * (1.f / 192.f);
    float vs = 0.f;
#pragma unroll
    for (int i = 0; i < 6; i++) { float d = v[i] - mu; vs += d * d; }
    vs = warpsum(vs);
    float rstd = rsqrtf(vs * (1.f / 192.f) + 1e-5f);
#pragma unroll
    for (int i = 0; i < 6; i++) {
        int c = lane + 32 * i;
        float val = (v[i] - mu) * rstd * g[c] + b[c];
        val = val * (1.f + cond[768 + c]) + cond[576 + c];
        split_store(g_A1, 384, (size_t)t, 192, c, val);
    }
}

// ---------------------------------------------------------------------------
// Tensor-core GEMM, cp.async 2-stage pipeline.
// Block tile 128x192, 8 warps (2x4), warp tile 64x48, K chunks of 64 bf16.
// Dynamic smem: 2 stages x (A 16KB + B 24KB) = 80KB.
// ---------------------------------------------------------------------------
#define STAGE_BYTES 40960
template <int MODE>
__global__ __launch_bounds__(256, 1) void k_tc_gemm(
    const __nv_bfloat16* __restrict__ A, const __nv_bfloat16* __restrict__ Bw,
    const float* __restrict__ bias, int Keff,
    float* __restrict__ fout, __nv_bfloat16* __restrict__ sout,
    const float* __restrict__ res, const float* __restrict__ cond) {
    extern __shared__ __align__(1024) unsigned char smem_dyn[];

    const int tid = threadIdx.x;
    const int lane = tid & 31;
    const int wid = tid >> 5;
    const int warp_m = (wid & 1) * 64;
    const int warp_n = (wid >> 1) * 48;

    const int rowbase = blockIdx.y * 128;
    const int colbase = blockIdx.x * 192;
    const int nchunks = Keff >> 6;

    const __nv_bfloat16* Arow = A + (size_t)rowbase * Keff;
    const __nv_bfloat16* Brow = Bw + (size_t)colbase * Keff;

    float acc[4][6][4];
#pragma unroll
    for (int mt = 0; mt < 4; mt++)
#pragma unroll
        for (int nt = 0; nt < 6; nt++)
#pragma unroll
            for (int i = 0; i < 4; i++) acc[mt][nt][i] = 0.f;

    int ar[4], as_[4], br[6], bs_[6];
#pragma unroll
    for (int i = 0; i < 4; i++) {
        int idx = tid + i * 256;
        ar[i] = idx >> 3; as_[i] = idx & 7;
    }
#pragma unroll
    for (int i = 0; i < 6; i++) {
        int idx = tid + i * 256;
        br[i] = idx >> 3; bs_[i] = idx & 7;
    }

    const uint32_t smem_u = cvta_smem(smem_dyn);

    auto issue = [&](int ch) {
        uint32_t sa = smem_u + (ch & 1) * STAGE_BYTES;
        uint32_t sb = sa + 16384;
        const __nv_bfloat16* Ach = Arow + ch * 64;
        const __nv_bfloat16* Bch = Brow + ch * 64;
#pragma unroll
        for (int i = 0; i < 4; i++)
            cp16(sa + (uint32_t)(ar[i] * 128 + ((as_[i] ^ (ar[i] & 7)) << 4)),
                 Ach + (size_t)ar[i] * Keff + as_[i] * 8);
#pragma unroll
        for (int i = 0; i < 6; i++)
            cp16(sb + (uint32_t)(br[i] * 128 + ((bs_[i] ^ (br[i] & 7)) << 4)),
                 Bch + (size_t)br[i] * Keff + bs_[i] * 8);
        asm volatile("cp.async.commit_group;");
    };

    issue(0);

    for (int ch = 0; ch < nchunks; ch++) {
        if (ch + 1 < nchunks) {
            issue(ch + 1);
            asm volatile("cp.async.wait_group 1;");
        } else {
            asm volatile("cp.async.wait_group 0;");
        }
        __syncthreads();

        uint32_t sa = smem_u + (ch & 1) * STAGE_BYTES;
        uint32_t sb = sa + 16384;

#pragma unroll
        for (int kk = 0; kk < 4; kk++) {
            uint32_t af[4][4];
#pragma unroll
            for (int mt = 0; mt < 4; mt++) {
                int r = warp_m + mt * 16 + (lane & 15);
                int seg = kk * 2 + (lane >> 4);
                uint32_t addr = sa + r * 128 + (((seg ^ (r & 7)) & 7) << 4);
                asm volatile(
                    "ldmatrix.sync.aligned.m8n8.x4.shared.b16 {%0,%1,%2,%3}, [%4];"
                    : "=r"(af[mt][0]), "=r"(af[mt][1]), "=r"(af[mt][2]), "=r"(af[mt][3])
                    : "r"(addr));
            }
            uint32_t bf[6][2];
#pragma unroll
            for (int nt = 0; nt < 6; nt++) {
                int r = warp_n + nt * 8 + (lane & 7);
                int seg = kk * 2 + ((lane >> 3) & 1);
                uint32_t addr = sb + r * 128 + (((seg ^ (r & 7)) & 7) << 4);
                asm volatile(
                    "ldmatrix.sync.aligned.m8n8.x2.shared.b16 {%0,%1}, [%2];"
                    : "=r"(bf[nt][0]), "=r"(bf[nt][1])
                    : "r"(addr));
            }
#pragma unroll
            for (int mt = 0; mt < 4; mt++)
#pragma unroll
                for (int nt = 0; nt < 6; nt++) {
                    asm volatile(
                        "mma.sync.aligned.m16n8k16.row.col.f32.bf16.bf16.f32 "
                        "{%0,%1,%2,%3}, {%4,%5,%6,%7}, {%8,%9}, {%0,%1,%2,%3};"
                        : "+f"(acc[mt][nt][0]), "+f"(acc[mt][nt][1]),
                          "+f"(acc[mt][nt][2]), "+f"(acc[mt][nt][3])
                        : "r"(af[mt][0]), "r"(af[mt][1]), "r"(af[mt][2]), "r"(af[mt][3]),
                          "r"(bf[nt][0]), "r"(bf[nt][1]));
                }
        }
        __syncthreads();
    }

    // -------------------- epilogue --------------------
#pragma unroll
    for (int mt = 0; mt < 4; mt++) {
#pragma unroll
        for (int half = 0; half < 2; half++) {
            int row = rowbase + warp_m + mt * 16 + (lane >> 2) + half * 8;
            int orow = 0;
            if (MODE == 1) orow = win_to_orig(row / NLOC, row % NLOC);
#pragma unroll
            for (int nt = 0; nt < 6; nt++) {
#pragma unroll
                for (int e = 0; e < 2; e++) {
                    float v = acc[mt][nt][half * 2 + e];
                    int c = colbase + warp_n + nt * 8 + (lane & 3) * 2 + e;
                    if (MODE == 0) {
                        fout[(size_t)row * 576 + c] = v + bias[c];
                    } else if (MODE == 1) {
                        float val = v + bias[c];
                        fout[(size_t)orow * 192 + c] =
                            res[(size_t)orow * 192 + c] + cond[384 + c] * val;
                    } else if (MODE == 2) {
                        float xg = v + bias[c];
                        float gl = 0.5f * xg * (1.f + erff(xg * 0.70710678118654752f));
                        split_store(sout, 1536, (size_t)row, 768, c, gl);
                    } else {
                        float val = v + bias[c];
                        fout[(size_t)row * 192 + c] =
                            res[(size_t)row * 192 + c] + cond[960 + c] * val;
                    }
                }
            }
        }
    }
}

// ---------------------------------------------------------------------------
// K3: fused window attention (fp32; writes split bf16 for proj GEMM)
// ---------------------------------------------------------------------------
__global__ __launch_bounds__(160) void k_attn(const float* __restrict__ qkv,
                                              const float* __restrict__ bias_table) {
    int w = blockIdx.x / NHEADS;
    int head = blockIdx.x - w * NHEADS;
    __shared__ float ks[NLOC][32];
    __shared__ float vs[NLOC][32];
    __shared__ float qs[NLOC][33];
    __shared__ int cmi[NLOC];
    __shared__ int lblm[NLOC];

    int tid = threadIdx.x;
    const float* base = qkv + (size_t)w * NLOC * 576;

    for (int idx = tid; idx < NLOC * 8; idx += 160) {
        int row = idx >> 3, f = idx & 7;
        const float* rb = base + (size_t)row * 576 + head * 32 + f * 4;
        float4 qv = *(const float4*)(rb);
        float4 kv = *(const float4*)(rb + 192);
        float4 vv = *(const float4*)(rb + 384);
        qs[row][f * 4 + 0] = qv.x; qs[row][f * 4 + 1] = qv.y;
        qs[row][f * 4 + 2] = qv.z; qs[row][f * 4 + 3] = qv.w;
        *(float4*)&ks[row][f * 4] = kv;
        *(float4*)&vs[row][f * 4] = vv;
    }
    int ih = (w / NL) % NH, iz = w / (NL * NH);
    if (tid < NLOC) {
        int z = tid / 72, hh = (tid / 12) % 6, l = tid % 12;
        cmi[tid] = 1656 * z + 138 * hh - l;
        int gz = iz * WS0 + z, gh = ih * WS1 + hh;
        int zseg = gz < 6 ? 0 : (gz < 7 ? 1 : 2);
        int hseg = gh < 54 ? 0 : (gh < 57 ? 1 : 2);
        lblm[tid] = zseg * 3 + hseg;
    }
    __syncthreads();

    if (tid < NLOC) {
        float q[32];
#pragma unroll
        for (int d = 0; d < 32; d++) q[d] = qs[tid][d] * 0.17677669529663687f;
        int z1 = tid / 72, h1 = (tid / 12) % 6, l1 = tid % 12;
        int cn = 828 * z1 + 23 * h1 + l1 + 11;
        int mylbl = lblm[tid];
        int typ = iz * NH + ih;
        const float* bt = bias_table + typ * NHEADS + head;

        float acc[32];
#pragma unroll
        for (int d = 0; d < 32; d++) acc[d] = 0.f;
        float mrun = -1e30f, lrun = 0.f;

        for (int m = 0; m < NLOC; m++) {
            float s = 0.f;
#pragma unroll
            for (int f = 0; f < 8; f++) {
                float4 kk = *(const float4*)&ks[m][f * 4];
                s = fmaf(q[f * 4 + 0], kk.x, s);
                s = fmaf(q[f * 4 + 1], kk.y, s);
                s = fmaf(q[f * 4 + 2], kk.z, s);
                s = fmaf(q[f * 4 + 3], kk.w, s);
            }
            int pidx = cn + cmi[m];
            s += __ldg(bt + (size_t)pidx * 240);
            if (lblm[m] != mylbl) s -= 100.f;

            if (s > mrun) {
                float corr = __expf(mrun - s);
                lrun = lrun * corr + 1.f;
#pragma unroll
                for (int d = 0; d < 32; d++)
                    acc[d] = fmaf(acc[d], corr, vs[m][d]);
                mrun = s;
            } else {
                float p = __expf(s - mrun);
                lrun += p;
#pragma unroll
                for (int d = 0; d < 32; d++)
                    acc[d] = fmaf(p, vs[m][d], acc[d]);
            }
        }
        float inv = 1.f / lrun;
        size_t row = (size_t)(w * NLOC + tid);
        int c0 = head * 32;
#pragma unroll
        for (int d = 0; d < 32; d++) {
            float o = acc[d] * inv;
            split_store(g_Aattn, 384, row, 192, c0 + d, o);
        }
    }
}

// ---------------------------------------------------------------------------
// Launch
// ---------------------------------------------------------------------------
extern "C" void kernel_launch(void* const* d_in, const int* in_sizes, int n_in,
                              void* d_out, int out_size) {
    const float* x          = (const float*)d_in[0];
    const float* cond       = (const float*)d_in[1];
    const float* g1         = (const float*)d_in[2];
    const float* bt1        = (const float*)d_in[3];
    const float* w_qkv      = (const float*)d_in[4];
    const float* b_qkv      = (const float*)d_in[5];
    const float* bias_table = (const float*)d_in[6];
    const float* w_proj     = (const float*)d_in[7];
    const float* b_proj     = (const float*)d_in[8];
    const float* g2         = (const float*)d_in[9];
    const float* bt2        = (const float*)d_in[10];
    const float* w_fc1      = (const float*)d_in[11];
    const float* b_fc1      = (const float*)d_in[12];
    const float* w_fc2      = (const float*)d_in[13];
    const float* b_fc2      = (const float*)d_in[14];
    float* out = (float*)d_out;

    __nv_bfloat16 *a1, *aat, *a2, *bq, *bp, *bf1, *bf2;
    float *qkvb, *yb;
    cudaGetSymbolAddress((void**)&a1, g_A1);
    cudaGetSymbolAddress((void**)&qkvb, g_qkv);
    cudaGetSymbolAddress((void**)&aat, g_Aattn);
    cudaGetSymbolAddress((void**)&yb, g_y);
    cudaGetSymbolAddress((void**)&a2, g_A2);
    cudaGetSymbolAddress((void**)&bq, g_Bqkv);
    cudaGetSymbolAddress((void**)&bp, g_Bproj);
    cudaGetSymbolAddress((void**)&bf1, g_Bfc1);
    cudaGetSymbolAddress((void**)&bf2, g_Bfc2);

    static bool attr_done = false;
    if (!attr_done) {
        cudaFuncSetAttribute(k_tc_gemm<0>,
                             cudaFuncAttributeMaxDynamicSharedMemorySize, 2 * STAGE_BYTES);
        cudaFuncSetAttribute(k_tc_gemm<1>,
                             cudaFuncAttributeMaxDynamicSharedMemorySize, 2 * STAGE_BYTES);
        cudaFuncSetAttribute(k_tc_gemm<2>,
                             cudaFuncAttributeMaxDynamicSharedMemorySize, 2 * STAGE_BYTES);
        cudaFuncSetAttribute(k_tc_gemm<3>,
                             cudaFuncAttributeMaxDynamicSharedMemorySize, 2 * STAGE_BYTES);
        attr_done = true;
    }

    // Weight split/transpose
    k_wprep<<<(192 * 576 + 255) / 256, 256>>>(w_qkv, bq, 192, 576);
    k_wprep<<<(192 * 192 + 255) / 256, 256>>>(w_proj, bp, 192, 192);
    k_wprep<<<(192 * 768 + 255) / 256, 256>>>(w_fc1, bf1, 192, 768);
    k_wprep<<<(768 * 192 + 255) / 256, 256>>>(w_fc2, bf2, 768, 192);

    // 1. LN1 + modulate + window gather -> split A'
    k_ln1<<<NTOK / 8, 256>>>(x, cond, g1, bt1);

    // 2. QKV GEMM: (57600,192) @ (192,576)
    k_tc_gemm<0><<<dim3(3, NTOK / 128), 256, 2 * STAGE_BYTES>>>(
        a1, bq, b_qkv, 384, qkvb, nullptr, nullptr, nullptr);

    // 3. Window attention -> split A'
    k_attn<<<NWIN * NHEADS, 160>>>(qkvb, bias_table);

    // 4. Proj GEMM + scatter + gated residual -> y
    k_tc_gemm<1><<<dim3(1, NTOK / 128), 256, 2 * STAGE_BYTES>>>(
        aat, bp, b_proj, 384, yb, nullptr, x, cond);

    // 5. LN2 + modulate -> split A'
    k_ln2<<<NTOK / 8, 256>>>(cond, g2, bt2);

    // 6. FC1 GEMM + GeLU -> split A2'
    k_tc_gemm<2><<<dim3(4, NTOK / 128), 256, 2 * STAGE_BYTES>>>(
        a1, bf1, b_fc1, 384, nullptr, a2, nullptr, nullptr);

    // 7. FC2 GEMM + gated residual -> out
    k_tc_gemm<3><<<dim3(1, NTOK / 128), 256, 2 * STAGE_BYTES>>>(
        a2, bf2, b_fc2, 1536, out, nullptr, yb, cond);
}